// round 13
// baseline (speedup 1.0000x reference)
#include <cuda_runtime.h>
#include <math.h>
#include <stdint.h>

#define MAX_N  1024
#define MAX_P  32768           // directed edges upper bound
#define EPS    1e-4f
#define ZCHUNK 32768           // bytes per bulk store
#define ZGRID  296             // 2 CTAs per SM (148 SMs): low smem footprint

// ---- scratch (__device__ globals; no allocation allowed) ----
__device__ float g_diag [MAX_N * 64];           // per-node sum of R^T R
__device__ float g_dis  [MAX_N * 64];           // per-node D^{-1/2}
__device__ float g_norm [MAX_P * 64];           // N_p = R_p @ Dis[head(p)]
__device__ float g_stage[(MAX_P + MAX_N) * 64]; // staged nonzero 8x8 blocks

// ---- persistent TMA bulk-store zero: 296 CTAs, each loops over its chunks.
//      One 32KB all-zero smem buffer reused for every store (contents static,
//      so all bulk stores may be concurrently in flight; one commit+wait). ----
__global__ void k_zero_tma(char* __restrict__ out, size_t total) {
    __shared__ __align__(128) char buf[ZCHUNK];
    float4* b4 = (float4*)buf;
    for (int t = threadIdx.x; t < ZCHUNK / 16; t += blockDim.x)
        b4[t] = make_float4(0.f, 0.f, 0.f, 0.f);
    __syncthreads();
    asm volatile("fence.proxy.async.shared::cta;" ::: "memory");
    if (threadIdx.x == 0) {
        uint32_t saddr;
        asm("{ .reg .u64 t; cvta.to.shared.u64 t, %1; cvt.u32.u64 %0, t; }"
            : "=r"(saddr) : "l"(buf));
        size_t nchunks = (total + ZCHUNK - 1) / ZCHUNK;
        // strided assignment: CTA b does chunks b, b+G, b+2G, ...
        for (size_t k = blockIdx.x; k < nchunks; k += gridDim.x) {
            size_t off = k * (size_t)ZCHUNK;
            size_t rem = total - off;
            unsigned len = (unsigned)(rem >= ZCHUNK ? ZCHUNK : rem);
            asm volatile(
                "cp.async.bulk.global.shared::cta.bulk_group [%0], [%1], %2;"
                :: "l"(out + off), "r"(saddr), "r"(len) : "memory");
        }
        asm volatile("cp.async.bulk.commit_group;" ::: "memory");
        asm volatile("cp.async.bulk.wait_group 0;" ::: "memory");
    }
}

// ---- k_ftf: smem-staged R^T R, atomically accumulated into g_diag[i] ----
__global__ void k_ftf(const float* __restrict__ R, const int* __restrict__ E, int P) {
    __shared__ float Rs[4][64];
    int sub = threadIdx.x >> 6;
    int t   = threadIdx.x & 63;
    int p   = blockIdx.x * 4 + sub;
    bool valid = (p < P);
    if (valid && t < 16)
        ((float4*)Rs[sub])[t] = ((const float4*)(R + (size_t)p * 64))[t];
    __syncthreads();
    if (!valid) return;
    int r = t >> 3, c = t & 7;
    float v = 0.f;
#pragma unroll
    for (int k = 0; k < 8; k++) v += Rs[sub][k * 8 + r] * Rs[sub][k * 8 + c];
    int i = E[2 * p];
    atomicAdd(&g_diag[i * 64 + t], v);
}

// ---- per-node D^{-1/2} via coupled Newton-Schulz; 4 nodes per 256-thread CTA ----
__global__ void k_ns(int n) {
    __shared__ float Y[4][64], Z[4][64], G[4][64], red[4][64];
    int sub = threadIdx.x >> 6;
    int t   = threadIdx.x & 63;
    int v   = blockIdx.x * 4 + sub;
    int vc  = (v < n) ? v : (n - 1);
    int r = t >> 3, c = t & 7;

    float a = g_diag[vc * 64 + r * 8 + c];
    float b = g_diag[vc * 64 + c * 8 + r];
    float d = 0.5f * (a + b) + ((r == c) ? EPS : 0.f);

    red[sub][t] = d * d;
    __syncthreads();
    if (t < 32) red[sub][t] += red[sub][t + 32];
    __syncthreads();
    if (t < 16) red[sub][t] += red[sub][t + 16];
    __syncthreads();
    if (t < 8)  red[sub][t] += red[sub][t + 8];
    __syncthreads();
    if (t < 4)  red[sub][t] += red[sub][t + 4];
    __syncthreads();
    if (t < 2)  red[sub][t] += red[sub][t + 2];
    __syncthreads();
    if (t == 0) red[sub][0] += red[sub][1];
    __syncthreads();
    float s = sqrtf(red[sub][0]);
    float inv_s = 1.f / s;

    Y[sub][t] = d * inv_s;
    Z[sub][t] = (r == c) ? 1.f : 0.f;
    __syncthreads();

    for (int it = 0; it < 24; it++) {
        float acc = 0.f;
#pragma unroll
        for (int k = 0; k < 8; k++) acc += Z[sub][r * 8 + k] * Y[sub][k * 8 + c];
        float g = ((r == c) ? 1.5f : 0.f) - 0.5f * acc;
        __syncthreads();
        G[sub][t] = g;
        __syncthreads();
        float ny = 0.f, nz = 0.f;
#pragma unroll
        for (int k = 0; k < 8; k++) {
            ny += Y[sub][r * 8 + k] * G[sub][k * 8 + c];
            nz += G[sub][r * 8 + k] * Z[sub][k * 8 + c];
        }
        __syncthreads();
        Y[sub][t] = ny;
        Z[sub][t] = nz;
        __syncthreads();
    }

    if (v < n) g_dis[v * 64 + t] = Z[sub][t] * rsqrtf(s);
}

// ---- k_norm: N_p = R_p @ Dis[head(p)] for every directed edge ----
__global__ void k_norm(const float* __restrict__ R, const int* __restrict__ E, int P) {
    __shared__ float Rs[4][64], Ds[4][64];
    int sub = threadIdx.x >> 6;
    int t   = threadIdx.x & 63;
    int p   = blockIdx.x * 4 + sub;
    bool valid = (p < P);
    if (valid) {
        int j = E[2 * p + 1];            // head
        if (t < 16)
            ((float4*)Rs[sub])[t] = ((const float4*)(R + (size_t)p * 64))[t];
        else if (t < 32)
            ((float4*)Ds[sub])[t - 16] = ((const float4*)(g_dis + (size_t)j * 64))[t - 16];
    }
    __syncthreads();
    if (!valid) return;
    int r = t >> 3, c = t & 7;
    float4 a0 = ((const float4*)(Rs[sub] + r * 8))[0];
    float4 a1 = ((const float4*)(Rs[sub] + r * 8))[1];
    const float* Dc = Ds[sub] + c;
    float s = a0.x * Dc[0]  + a0.y * Dc[8]  + a0.z * Dc[16] + a0.w * Dc[24]
            + a1.x * Dc[32] + a1.y * Dc[40] + a1.z * Dc[48] + a1.w * Dc[56];
    g_norm[(size_t)p * 64 + t] = s;
}

// ---- stage edge blocks: -sgn * N_rev^T @ N_p (ONE matmul per block) ----
__global__ void k_stage_e(const int* __restrict__ E, const float* __restrict__ L1,
                          int P, int n) {
    __shared__ float M1T[4][64], M2[4][64];
    int sub = threadIdx.x >> 6;
    int t   = threadIdx.x & 63;
    int p   = blockIdx.x * 4 + sub;
    bool valid = (p < P);
    int i = 0, j = 0;
    if (valid) {
        int2 e = ((const int2*)E)[p];
        i = e.x; j = e.y;
        int half = P >> 1;
        int rev = (p < half) ? (p + half) : (p - half);
        if (t < 16) {
            float4 v = ((const float4*)(g_norm + (size_t)rev * 64))[t];
            int row = t >> 1, c0 = (t & 1) * 4;
            M1T[sub][(c0 + 0) * 8 + row] = v.x;
            M1T[sub][(c0 + 1) * 8 + row] = v.y;
            M1T[sub][(c0 + 2) * 8 + row] = v.z;
            M1T[sub][(c0 + 3) * 8 + row] = v.w;
        } else if (t < 32) {
            ((float4*)M2[sub])[t - 16] = ((const float4*)(g_norm + (size_t)p * 64))[t - 16];
        }
    }
    __syncthreads();
    if (!valid) return;
    float l = L1[(size_t)i * n + j];
    float sgn = (l > 0.f) ? 1.f : ((l < 0.f) ? -1.f : 0.f);
    int r = t >> 3, c = t & 7;
    float4 a0 = ((const float4*)(M1T[sub] + r * 8))[0];
    float4 a1 = ((const float4*)(M1T[sub] + r * 8))[1];
    const float* Bc = M2[sub] + c;
    float s = a0.x * Bc[0]  + a0.y * Bc[8]  + a0.z * Bc[16] + a0.w * Bc[24]
            + a1.x * Bc[32] + a1.y * Bc[40] + a1.z * Bc[48] + a1.w * Bc[56];
    g_stage[(size_t)p * 64 + t] = -sgn * s;
}

// ---- stage diagonal blocks: Dis_v @ diag_v @ Dis_v (n blocks) ----
__global__ void k_stage_d(int P, int n) {
    __shared__ float Di[4][64], B[4][64], T[4][64];
    int sub = threadIdx.x >> 6;
    int t   = threadIdx.x & 63;
    int v   = blockIdx.x * 4 + sub;
    bool valid = (v < n);
    if (valid) {
        if (t < 16)
            ((float4*)Di[sub])[t] = ((const float4*)(g_dis + (size_t)v * 64))[t];
        else if (t < 32)
            ((float4*)B[sub])[t - 16] = ((const float4*)(g_diag + (size_t)v * 64))[t - 16];
    }
    __syncthreads();
    int r = t >> 3, c = t & 7;
    if (valid) {
        float4 a0 = ((const float4*)(Di[sub] + r * 8))[0];
        float4 a1 = ((const float4*)(Di[sub] + r * 8))[1];
        const float* Bc = B[sub] + c;
        float s = a0.x * Bc[0]  + a0.y * Bc[8]  + a0.z * Bc[16] + a0.w * Bc[24]
                + a1.x * Bc[32] + a1.y * Bc[40] + a1.z * Bc[48] + a1.w * Bc[56];
        T[sub][t] = s;
    }
    __syncthreads();
    if (valid) {
        float4 a0 = ((const float4*)(T[sub] + r * 8))[0];
        float4 a1 = ((const float4*)(T[sub] + r * 8))[1];
        const float* Bc = Di[sub] + c;
        float s = a0.x * Bc[0]  + a0.y * Bc[8]  + a0.z * Bc[16] + a0.w * Bc[24]
                + a1.x * Bc[32] + a1.y * Bc[40] + a1.z * Bc[48] + a1.w * Bc[56];
        g_stage[(size_t)(P + v) * 64 + t] = s;
    }
}

// ---- scatter: copy staged blocks into the zeroed output (tiny tail) ----
__global__ void k_scatter(const int* __restrict__ E, float* __restrict__ out,
                          int P, int n) {
    int bid = blockIdx.x * 16 + (threadIdx.x >> 4);
    if (bid >= P + n) return;
    int l = threadIdx.x & 15;     // 0..15: (row, half)
    int r = l >> 1, h = l & 1;
    int i, j;
    if (bid < P) { int2 e = ((const int2*)E)[bid]; i = e.x; j = e.y; }
    else         { i = j = bid - P; }
    float4 v = ((const float4*)(g_stage + (size_t)bid * 64))[l];
    size_t nd = (size_t)n * 8;
    ((float4*)(out + ((size_t)i * 8 + r) * nd + (size_t)j * 8))[h] = v;
}

extern "C" void kernel_launch(void* const* d_in, const int* in_sizes, int n_in,
                              void* d_out, int out_size) {
    const float* R  = (const float*)d_in[0];  // (P, 8, 8)
    const int*   E  = (const int*)  d_in[1];  // (P, 2)
    const float* L1 = (const float*)d_in[3];  // (n, n)

    int P = in_sizes[1] / 2;
    int n = (int)(sqrt((double)in_sizes[3]) + 0.5);

    // one-time host-side resources (streams/events are NOT device memory)
    static bool inited = false;
    static cudaStream_t side;
    static cudaEvent_t ev_fork, ev_chain;
    static void* diag_ptr;
    if (!inited) {
        cudaStreamCreateWithFlags(&side, cudaStreamNonBlocking);
        cudaEventCreateWithFlags(&ev_fork, cudaEventDisableTiming);
        cudaEventCreateWithFlags(&ev_chain, cudaEventDisableTiming);
        cudaGetSymbolAddress(&diag_ptr, g_diag);
        inited = true;
    }

    // side stream (forked at t=0, launched FIRST so chain CTAs co-reside
    // with the low-footprint zero CTAs): chain + stage — never touches d_out
    cudaEventRecord(ev_fork, 0);
    cudaStreamWaitEvent(side, ev_fork, 0);
    cudaMemsetAsync(diag_ptr, 0, (size_t)n * 64 * sizeof(float), side);
    k_ftf    <<<(P + 3) / 4, 256, 0, side>>>(R, E, P);
    k_ns     <<<(n + 3) / 4, 256, 0, side>>>(n);
    k_norm   <<<(P + 3) / 4, 256, 0, side>>>(R, E, P);
    k_stage_e<<<(P + 3) / 4, 256, 0, side>>>(E, L1, P, n);
    k_stage_d<<<(n + 3) / 4, 256, 0, side>>>(P, n);
    cudaEventRecord(ev_chain, side);

    // main stream: persistent TMA zero (2 CTAs/SM -> chain can co-schedule)
    size_t total = (size_t)out_size * sizeof(float);
    k_zero_tma<<<ZGRID, 128>>>((char*)d_out, total);

    // tiny tail: scatter staged blocks after zero + chain
    cudaStreamWaitEvent(0, ev_chain, 0);
    k_scatter<<<(P + n + 15) / 16, 256>>>(E, (float*)d_out, P, n);
}

// round 14
// speedup vs baseline: 1.2678x; 1.2678x over previous
#include <cuda_runtime.h>
#include <math.h>
#include <stdint.h>

#define MAX_N  1024
#define MAX_P  32768           // directed edges upper bound
#define EPS    1e-4f
#define ZCHUNK 8192            // bytes per bulk store (small smem footprint)
#define ZPER   16              // chunks per CTA -> 128KB per CTA

// ---- scratch (__device__ globals; no allocation allowed) ----
__device__ float g_diag [MAX_N * 64];           // per-node sum of R^T R
__device__ float g_dis  [MAX_N * 64];           // per-node D^{-1/2}
__device__ float g_norm [MAX_P * 64];           // N_p = R_p @ Dis[head(p)]
__device__ float g_stage[(MAX_P + MAX_N) * 64]; // staged nonzero 8x8 blocks

// ---- TMA bulk-store zero: 2048 CTAs x 32 threads x 8KB smem.
//      Low per-CTA footprint so chain kernels co-schedule on the same SMs. ----
__global__ void k_zero_tma(char* __restrict__ out, size_t total) {
    __shared__ __align__(128) char buf[ZCHUNK];
    float4* b4 = (float4*)buf;
    for (int t = threadIdx.x; t < ZCHUNK / 16; t += blockDim.x)
        b4[t] = make_float4(0.f, 0.f, 0.f, 0.f);
    __syncthreads();
    asm volatile("fence.proxy.async.shared::cta;" ::: "memory");
    if (threadIdx.x == 0) {
        uint32_t saddr;
        asm("{ .reg .u64 t; cvta.to.shared.u64 t, %1; cvt.u32.u64 %0, t; }"
            : "=r"(saddr) : "l"(buf));
        size_t base = (size_t)blockIdx.x * (ZPER * (size_t)ZCHUNK);
#pragma unroll
        for (int k = 0; k < ZPER; k++) {
            size_t off = base + (size_t)k * ZCHUNK;
            if (off >= total) break;
            size_t rem = total - off;
            unsigned len = (unsigned)(rem >= ZCHUNK ? ZCHUNK : rem);
            asm volatile(
                "cp.async.bulk.global.shared::cta.bulk_group [%0], [%1], %2;"
                :: "l"(out + off), "r"(saddr), "r"(len) : "memory");
        }
        asm volatile("cp.async.bulk.commit_group;" ::: "memory");
        asm volatile("cp.async.bulk.wait_group 0;" ::: "memory");
    }
}

// ---- k_ftf: smem-staged R^T R, atomically accumulated into g_diag[i] ----
__global__ void k_ftf(const float* __restrict__ R, const int* __restrict__ E, int P) {
    __shared__ float Rs[4][64];
    int sub = threadIdx.x >> 6;
    int t   = threadIdx.x & 63;
    int p   = blockIdx.x * 4 + sub;
    bool valid = (p < P);
    if (valid && t < 16)
        ((float4*)Rs[sub])[t] = ((const float4*)(R + (size_t)p * 64))[t];
    __syncthreads();
    if (!valid) return;
    int r = t >> 3, c = t & 7;
    float v = 0.f;
#pragma unroll
    for (int k = 0; k < 8; k++) v += Rs[sub][k * 8 + r] * Rs[sub][k * 8 + c];
    int i = E[2 * p];
    atomicAdd(&g_diag[i * 64 + t], v);
}

// ---- per-node D^{-1/2} via coupled Newton-Schulz; 4 nodes per 256-thread CTA ----
__global__ void k_ns(int n) {
    __shared__ float Y[4][64], Z[4][64], G[4][64], red[4][64];
    int sub = threadIdx.x >> 6;
    int t   = threadIdx.x & 63;
    int v   = blockIdx.x * 4 + sub;
    int vc  = (v < n) ? v : (n - 1);
    int r = t >> 3, c = t & 7;

    float a = g_diag[vc * 64 + r * 8 + c];
    float b = g_diag[vc * 64 + c * 8 + r];
    float d = 0.5f * (a + b) + ((r == c) ? EPS : 0.f);

    red[sub][t] = d * d;
    __syncthreads();
    if (t < 32) red[sub][t] += red[sub][t + 32];
    __syncthreads();
    if (t < 16) red[sub][t] += red[sub][t + 16];
    __syncthreads();
    if (t < 8)  red[sub][t] += red[sub][t + 8];
    __syncthreads();
    if (t < 4)  red[sub][t] += red[sub][t + 4];
    __syncthreads();
    if (t < 2)  red[sub][t] += red[sub][t + 2];
    __syncthreads();
    if (t == 0) red[sub][0] += red[sub][1];
    __syncthreads();
    float s = sqrtf(red[sub][0]);
    float inv_s = 1.f / s;

    Y[sub][t] = d * inv_s;
    Z[sub][t] = (r == c) ? 1.f : 0.f;
    __syncthreads();

    for (int it = 0; it < 24; it++) {
        float acc = 0.f;
#pragma unroll
        for (int k = 0; k < 8; k++) acc += Z[sub][r * 8 + k] * Y[sub][k * 8 + c];
        float g = ((r == c) ? 1.5f : 0.f) - 0.5f * acc;
        __syncthreads();
        G[sub][t] = g;
        __syncthreads();
        float ny = 0.f, nz = 0.f;
#pragma unroll
        for (int k = 0; k < 8; k++) {
            ny += Y[sub][r * 8 + k] * G[sub][k * 8 + c];
            nz += G[sub][r * 8 + k] * Z[sub][k * 8 + c];
        }
        __syncthreads();
        Y[sub][t] = ny;
        Z[sub][t] = nz;
        __syncthreads();
    }

    if (v < n) g_dis[v * 64 + t] = Z[sub][t] * rsqrtf(s);
}

// ---- k_norm: N_p = R_p @ Dis[head(p)] for every directed edge ----
__global__ void k_norm(const float* __restrict__ R, const int* __restrict__ E, int P) {
    __shared__ float Rs[4][64], Ds[4][64];
    int sub = threadIdx.x >> 6;
    int t   = threadIdx.x & 63;
    int p   = blockIdx.x * 4 + sub;
    bool valid = (p < P);
    if (valid) {
        int j = E[2 * p + 1];            // head
        if (t < 16)
            ((float4*)Rs[sub])[t] = ((const float4*)(R + (size_t)p * 64))[t];
        else if (t < 32)
            ((float4*)Ds[sub])[t - 16] = ((const float4*)(g_dis + (size_t)j * 64))[t - 16];
    }
    __syncthreads();
    if (!valid) return;
    int r = t >> 3, c = t & 7;
    float4 a0 = ((const float4*)(Rs[sub] + r * 8))[0];
    float4 a1 = ((const float4*)(Rs[sub] + r * 8))[1];
    const float* Dc = Ds[sub] + c;
    float s = a0.x * Dc[0]  + a0.y * Dc[8]  + a0.z * Dc[16] + a0.w * Dc[24]
            + a1.x * Dc[32] + a1.y * Dc[40] + a1.z * Dc[48] + a1.w * Dc[56];
    g_norm[(size_t)p * 64 + t] = s;
}

// ---- stage edge blocks: -sgn * N_rev^T @ N_p (ONE matmul per block) ----
__global__ void k_stage_e(const int* __restrict__ E, const float* __restrict__ L1,
                          int P, int n) {
    __shared__ float M1T[4][64], M2[4][64];
    int sub = threadIdx.x >> 6;
    int t   = threadIdx.x & 63;
    int p   = blockIdx.x * 4 + sub;
    bool valid = (p < P);
    int i = 0, j = 0;
    if (valid) {
        int2 e = ((const int2*)E)[p];
        i = e.x; j = e.y;
        int half = P >> 1;
        int rev = (p < half) ? (p + half) : (p - half);
        if (t < 16) {
            float4 v = ((const float4*)(g_norm + (size_t)rev * 64))[t];
            int row = t >> 1, c0 = (t & 1) * 4;
            M1T[sub][(c0 + 0) * 8 + row] = v.x;
            M1T[sub][(c0 + 1) * 8 + row] = v.y;
            M1T[sub][(c0 + 2) * 8 + row] = v.z;
            M1T[sub][(c0 + 3) * 8 + row] = v.w;
        } else if (t < 32) {
            ((float4*)M2[sub])[t - 16] = ((const float4*)(g_norm + (size_t)p * 64))[t - 16];
        }
    }
    __syncthreads();
    if (!valid) return;
    float l = L1[(size_t)i * n + j];
    float sgn = (l > 0.f) ? 1.f : ((l < 0.f) ? -1.f : 0.f);
    int r = t >> 3, c = t & 7;
    float4 a0 = ((const float4*)(M1T[sub] + r * 8))[0];
    float4 a1 = ((const float4*)(M1T[sub] + r * 8))[1];
    const float* Bc = M2[sub] + c;
    float s = a0.x * Bc[0]  + a0.y * Bc[8]  + a0.z * Bc[16] + a0.w * Bc[24]
            + a1.x * Bc[32] + a1.y * Bc[40] + a1.z * Bc[48] + a1.w * Bc[56];
    g_stage[(size_t)p * 64 + t] = -sgn * s;
}

// ---- stage diagonal blocks: Dis_v @ diag_v @ Dis_v (n blocks) ----
__global__ void k_stage_d(int P, int n) {
    __shared__ float Di[4][64], B[4][64], T[4][64];
    int sub = threadIdx.x >> 6;
    int t   = threadIdx.x & 63;
    int v   = blockIdx.x * 4 + sub;
    bool valid = (v < n);
    if (valid) {
        if (t < 16)
            ((float4*)Di[sub])[t] = ((const float4*)(g_dis + (size_t)v * 64))[t];
        else if (t < 32)
            ((float4*)B[sub])[t - 16] = ((const float4*)(g_diag + (size_t)v * 64))[t - 16];
    }
    __syncthreads();
    int r = t >> 3, c = t & 7;
    if (valid) {
        float4 a0 = ((const float4*)(Di[sub] + r * 8))[0];
        float4 a1 = ((const float4*)(Di[sub] + r * 8))[1];
        const float* Bc = B[sub] + c;
        float s = a0.x * Bc[0]  + a0.y * Bc[8]  + a0.z * Bc[16] + a0.w * Bc[24]
                + a1.x * Bc[32] + a1.y * Bc[40] + a1.z * Bc[48] + a1.w * Bc[56];
        T[sub][t] = s;
    }
    __syncthreads();
    if (valid) {
        float4 a0 = ((const float4*)(T[sub] + r * 8))[0];
        float4 a1 = ((const float4*)(T[sub] + r * 8))[1];
        const float* Bc = Di[sub] + c;
        float s = a0.x * Bc[0]  + a0.y * Bc[8]  + a0.z * Bc[16] + a0.w * Bc[24]
                + a1.x * Bc[32] + a1.y * Bc[40] + a1.z * Bc[48] + a1.w * Bc[56];
        g_stage[(size_t)(P + v) * 64 + t] = s;
    }
}

// ---- scatter: copy staged blocks into the zeroed output (tiny tail) ----
__global__ void k_scatter(const int* __restrict__ E, float* __restrict__ out,
                          int P, int n) {
    int bid = blockIdx.x * 16 + (threadIdx.x >> 4);
    if (bid >= P + n) return;
    int l = threadIdx.x & 15;     // 0..15: (row, half)
    int r = l >> 1, h = l & 1;
    int i, j;
    if (bid < P) { int2 e = ((const int2*)E)[bid]; i = e.x; j = e.y; }
    else         { i = j = bid - P; }
    float4 v = ((const float4*)(g_stage + (size_t)bid * 64))[l];
    size_t nd = (size_t)n * 8;
    ((float4*)(out + ((size_t)i * 8 + r) * nd + (size_t)j * 8))[h] = v;
}

extern "C" void kernel_launch(void* const* d_in, const int* in_sizes, int n_in,
                              void* d_out, int out_size) {
    const float* R  = (const float*)d_in[0];  // (P, 8, 8)
    const int*   E  = (const int*)  d_in[1];  // (P, 2)
    const float* L1 = (const float*)d_in[3];  // (n, n)

    int P = in_sizes[1] / 2;
    int n = (int)(sqrt((double)in_sizes[3]) + 0.5);

    // one-time host-side resources (streams/events are NOT device memory)
    static bool inited = false;
    static cudaStream_t side;
    static cudaEvent_t ev_fork, ev_chain;
    static void* diag_ptr;
    if (!inited) {
        cudaStreamCreateWithFlags(&side, cudaStreamNonBlocking);
        cudaEventCreateWithFlags(&ev_fork, cudaEventDisableTiming);
        cudaEventCreateWithFlags(&ev_chain, cudaEventDisableTiming);
        cudaGetSymbolAddress(&diag_ptr, g_diag);
        inited = true;
    }

    cudaEventRecord(ev_fork, 0);

    // main stream: low-footprint TMA zero (32 thr + 8KB smem per CTA ->
    // chain kernels can co-reside on the same SMs)
    size_t total = (size_t)out_size * sizeof(float);
    size_t per_cta = (size_t)ZPER * ZCHUNK;
    int zgrid = (int)((total + per_cta - 1) / per_cta);
    k_zero_tma<<<zgrid, 32>>>((char*)d_out, total);

    // side stream: chain + stage, co-scheduled with the zero
    cudaStreamWaitEvent(side, ev_fork, 0);
    cudaMemsetAsync(diag_ptr, 0, (size_t)n * 64 * sizeof(float), side);
    k_ftf    <<<(P + 3) / 4, 256, 0, side>>>(R, E, P);
    k_ns     <<<(n + 3) / 4, 256, 0, side>>>(n);
    k_norm   <<<(P + 3) / 4, 256, 0, side>>>(R, E, P);
    k_stage_e<<<(P + 3) / 4, 256, 0, side>>>(E, L1, P, n);
    k_stage_d<<<(n + 3) / 4, 256, 0, side>>>(P, n);
    cudaEventRecord(ev_chain, side);

    // tiny tail: scatter staged blocks after zero + chain
    cudaStreamWaitEvent(0, ev_chain, 0);
    k_scatter<<<(P + n + 15) / 16, 256>>>(E, (float*)d_out, P, n);
}

// round 15
// speedup vs baseline: 1.4833x; 1.1700x over previous
#include <cuda_runtime.h>
#include <math.h>
#include <stdint.h>

#define MAX_N  1024
#define EPS    1e-4f
#define ZCHUNK 32768           // bytes per bulk store (proven-fast config)
#define ZPER   4               // chunks per CTA

// ---- scratch (__device__ globals; no allocation allowed) ----
__device__ float g_diag[MAX_N * 64];    // per-node sum of R^T R
__device__ float g_dis [MAX_N * 64];    // per-node D^{-1/2}

// ---- TMA bulk-store zero (R11 exact config: 2048 CTAs x 128 thr x 32KB) ----
__global__ void k_zero_tma(char* __restrict__ out, size_t total) {
    __shared__ __align__(128) char buf[ZCHUNK];
    float4* b4 = (float4*)buf;
    for (int t = threadIdx.x; t < ZCHUNK / 16; t += blockDim.x)
        b4[t] = make_float4(0.f, 0.f, 0.f, 0.f);
    __syncthreads();
    asm volatile("fence.proxy.async.shared::cta;" ::: "memory");
    if (threadIdx.x == 0) {
        uint32_t saddr;
        asm("{ .reg .u64 t; cvta.to.shared.u64 t, %1; cvt.u32.u64 %0, t; }"
            : "=r"(saddr) : "l"(buf));
        size_t base = (size_t)blockIdx.x * (ZPER * (size_t)ZCHUNK);
#pragma unroll
        for (int k = 0; k < ZPER; k++) {
            size_t off = base + (size_t)k * ZCHUNK;
            if (off >= total) break;
            size_t rem = total - off;
            unsigned len = (unsigned)(rem >= ZCHUNK ? ZCHUNK : rem);
            asm volatile(
                "cp.async.bulk.global.shared::cta.bulk_group [%0], [%1], %2;"
                :: "l"(out + off), "r"(saddr), "r"(len) : "memory");
        }
        asm volatile("cp.async.bulk.commit_group;" ::: "memory");
        asm volatile("cp.async.bulk.wait_group 0;" ::: "memory");
    }
}

// ---- k_ftf: smem-staged R^T R, atomically accumulated into g_diag[i] ----
__global__ void k_ftf(const float* __restrict__ R, const int* __restrict__ E, int P) {
    __shared__ float Rs[4][64];
    int sub = threadIdx.x >> 6;
    int t   = threadIdx.x & 63;
    int p   = blockIdx.x * 4 + sub;
    bool valid = (p < P);
    if (valid && t < 16)
        ((float4*)Rs[sub])[t] = ((const float4*)(R + (size_t)p * 64))[t];
    __syncthreads();
    if (!valid) return;
    int r = t >> 3, c = t & 7;
    float v = 0.f;
#pragma unroll
    for (int k = 0; k < 8; k++) v += Rs[sub][k * 8 + r] * Rs[sub][k * 8 + c];
    int i = E[2 * p];
    atomicAdd(&g_diag[i * 64 + t], v);
}

// ---- per-node D^{-1/2} via coupled Newton-Schulz; 4 nodes per 256-thread CTA ----
__global__ void k_ns(int n) {
    __shared__ float Y[4][64], Z[4][64], G[4][64], red[4][64];
    int sub = threadIdx.x >> 6;
    int t   = threadIdx.x & 63;
    int v   = blockIdx.x * 4 + sub;
    int vc  = (v < n) ? v : (n - 1);
    int r = t >> 3, c = t & 7;

    float a = g_diag[vc * 64 + r * 8 + c];
    float b = g_diag[vc * 64 + c * 8 + r];
    float d = 0.5f * (a + b) + ((r == c) ? EPS : 0.f);

    red[sub][t] = d * d;
    __syncthreads();
    if (t < 32) red[sub][t] += red[sub][t + 32];
    __syncthreads();
    if (t < 16) red[sub][t] += red[sub][t + 16];
    __syncthreads();
    if (t < 8)  red[sub][t] += red[sub][t + 8];
    __syncthreads();
    if (t < 4)  red[sub][t] += red[sub][t + 4];
    __syncthreads();
    if (t < 2)  red[sub][t] += red[sub][t + 2];
    __syncthreads();
    if (t == 0) red[sub][0] += red[sub][1];
    __syncthreads();
    float s = sqrtf(red[sub][0]);
    float inv_s = 1.f / s;

    Y[sub][t] = d * inv_s;
    Z[sub][t] = (r == c) ? 1.f : 0.f;
    __syncthreads();

    for (int it = 0; it < 24; it++) {
        float acc = 0.f;
#pragma unroll
        for (int k = 0; k < 8; k++) acc += Z[sub][r * 8 + k] * Y[sub][k * 8 + c];
        float g = ((r == c) ? 1.5f : 0.f) - 0.5f * acc;
        __syncthreads();
        G[sub][t] = g;
        __syncthreads();
        float ny = 0.f, nz = 0.f;
#pragma unroll
        for (int k = 0; k < 8; k++) {
            ny += Y[sub][r * 8 + k] * G[sub][k * 8 + c];
            nz += G[sub][r * 8 + k] * Z[sub][k * 8 + c];
        }
        __syncthreads();
        Y[sub][t] = ny;
        Z[sub][t] = nz;
        __syncthreads();
    }

    if (v < n) g_dis[v * 64 + t] = Z[sub][t] * rsqrtf(s);
}

// ---- k_edges (FUSED): per edge p, write directly to d_out:
//      block(i,j) = -sgn * (R_rev @ Dis_i)^T @ (R_p @ Dis_j)
//      4 edges per 256-thread CTA; one pass, no staging. ----
__global__ void k_edges(const float* __restrict__ R, const int* __restrict__ E,
                        const float* __restrict__ L1, float* __restrict__ out,
                        int P, int n) {
    __shared__ float Rp[4][64], Rr[4][64], DiS[4][64], DjS[4][64], MT[4][64], NN[4][64];
    int sub = threadIdx.x >> 6;
    int t   = threadIdx.x & 63;
    int p   = blockIdx.x * 4 + sub;
    bool valid = (p < P);
    int i = 0, j = 0;

    if (valid) {
        int2 e = ((const int2*)E)[p];
        i = e.x; j = e.y;
        int half = P >> 1;
        int rev = (p < half) ? (p + half) : (p - half);
        int grp = t >> 4;      // 0..3: which operand this thread loads
        int l   = t & 15;      // float4 index
        if (grp == 0)      ((float4*)Rp[sub])[l]  = ((const float4*)(R + (size_t)p * 64))[l];
        else if (grp == 1) ((float4*)Rr[sub])[l]  = ((const float4*)(R + (size_t)rev * 64))[l];
        else if (grp == 2) ((float4*)DiS[sub])[l] = ((const float4*)(g_dis + (size_t)i * 64))[l];
        else               ((float4*)DjS[sub])[l] = ((const float4*)(g_dis + (size_t)j * 64))[l];
    }
    __syncthreads();

    int r = t >> 3, c = t & 7;
    if (valid) {
        // M[r][c] = sum_k Rr[r][k] * Dis_i[k][c]   (stored transposed)
        float4 a0 = ((const float4*)(Rr[sub] + r * 8))[0];
        float4 a1 = ((const float4*)(Rr[sub] + r * 8))[1];
        const float* Dc = DiS[sub] + c;
        float m = a0.x * Dc[0]  + a0.y * Dc[8]  + a0.z * Dc[16] + a0.w * Dc[24]
                + a1.x * Dc[32] + a1.y * Dc[40] + a1.z * Dc[48] + a1.w * Dc[56];
        // N[r][c] = sum_k Rp[r][k] * Dis_j[k][c]
        float4 b0 = ((const float4*)(Rp[sub] + r * 8))[0];
        float4 b1 = ((const float4*)(Rp[sub] + r * 8))[1];
        const float* Ec = DjS[sub] + c;
        float nn = b0.x * Ec[0]  + b0.y * Ec[8]  + b0.z * Ec[16] + b0.w * Ec[24]
                 + b1.x * Ec[32] + b1.y * Ec[40] + b1.z * Ec[48] + b1.w * Ec[56];
        MT[sub][c * 8 + r] = m;   // MT[x][y] = M[y][x]
        NN[sub][t] = nn;
    }
    __syncthreads();

    if (valid) {
        float l1v = L1[(size_t)i * n + j];
        float sgn = (l1v > 0.f) ? 1.f : ((l1v < 0.f) ? -1.f : 0.f);
        // block[r][c] = sum_k M[k][r] * N[k][c] = sum_k MT[r*8+k] * NN[k*8+c]
        float4 a0 = ((const float4*)(MT[sub] + r * 8))[0];
        float4 a1 = ((const float4*)(MT[sub] + r * 8))[1];
        const float* Bc = NN[sub] + c;
        float s = a0.x * Bc[0]  + a0.y * Bc[8]  + a0.z * Bc[16] + a0.w * Bc[24]
                + a1.x * Bc[32] + a1.y * Bc[40] + a1.z * Bc[48] + a1.w * Bc[56];
        size_t nd = (size_t)n * 8;
        out[((size_t)i * 8 + r) * nd + (size_t)j * 8 + c] = -sgn * s;
    }
}

// ---- k_diag: diagonal blocks Dis_v @ diag_v @ Dis_v, written directly ----
__global__ void k_diag(float* __restrict__ out, int n) {
    __shared__ float Di[4][64], B[4][64], T[4][64];
    int sub = threadIdx.x >> 6;
    int t   = threadIdx.x & 63;
    int v   = blockIdx.x * 4 + sub;
    bool valid = (v < n);
    if (valid) {
        if (t < 16)
            ((float4*)Di[sub])[t] = ((const float4*)(g_dis + (size_t)v * 64))[t];
        else if (t < 32)
            ((float4*)B[sub])[t - 16] = ((const float4*)(g_diag + (size_t)v * 64))[t - 16];
    }
    __syncthreads();
    int r = t >> 3, c = t & 7;
    if (valid) {
        float4 a0 = ((const float4*)(Di[sub] + r * 8))[0];
        float4 a1 = ((const float4*)(Di[sub] + r * 8))[1];
        const float* Bc = B[sub] + c;
        float s = a0.x * Bc[0]  + a0.y * Bc[8]  + a0.z * Bc[16] + a0.w * Bc[24]
                + a1.x * Bc[32] + a1.y * Bc[40] + a1.z * Bc[48] + a1.w * Bc[56];
        T[sub][t] = s;
    }
    __syncthreads();
    if (valid) {
        float4 a0 = ((const float4*)(T[sub] + r * 8))[0];
        float4 a1 = ((const float4*)(T[sub] + r * 8))[1];
        const float* Bc = Di[sub] + c;
        float s = a0.x * Bc[0]  + a0.y * Bc[8]  + a0.z * Bc[16] + a0.w * Bc[24]
                + a1.x * Bc[32] + a1.y * Bc[40] + a1.z * Bc[48] + a1.w * Bc[56];
        size_t nd = (size_t)n * 8;
        out[((size_t)v * 8 + r) * nd + (size_t)v * 8 + c] = s;
    }
}

extern "C" void kernel_launch(void* const* d_in, const int* in_sizes, int n_in,
                              void* d_out, int out_size) {
    const float* R  = (const float*)d_in[0];  // (P, 8, 8)
    const int*   E  = (const int*)  d_in[1];  // (P, 2)
    const float* L1 = (const float*)d_in[3];  // (n, n)

    int P = in_sizes[1] / 2;
    int n = (int)(sqrt((double)in_sizes[3]) + 0.5);

    // one-time host-side resources (streams/events are NOT device memory)
    static bool inited = false;
    static cudaStream_t side;
    static cudaEvent_t ev_fork, ev_chain;
    static void* diag_ptr;
    if (!inited) {
        cudaStreamCreateWithFlags(&side, cudaStreamNonBlocking);
        cudaEventCreateWithFlags(&ev_fork, cudaEventDisableTiming);
        cudaEventCreateWithFlags(&ev_chain, cudaEventDisableTiming);
        cudaGetSymbolAddress(&diag_ptr, g_diag);
        inited = true;
    }

    cudaEventRecord(ev_fork, 0);

    // side stream: ftf + ns (free if overlap happens, cheap if serial)
    cudaStreamWaitEvent(side, ev_fork, 0);
    cudaMemsetAsync(diag_ptr, 0, (size_t)n * 64 * sizeof(float), side);
    k_ftf<<<(P + 3) / 4, 256, 0, side>>>(R, E, P);
    k_ns <<<(n + 3) / 4, 256, 0, side>>>(n);
    cudaEventRecord(ev_chain, side);

    // main stream: TMA zero (proven 4.9 TB/s config)
    size_t total = (size_t)out_size * sizeof(float);
    size_t per_cta = (size_t)ZPER * ZCHUNK;
    int zgrid = (int)((total + per_cta - 1) / per_cta);
    k_zero_tma<<<zgrid, 128>>>((char*)d_out, total);

    // tail: fused edge writer + diag writer, directly into d_out
    cudaStreamWaitEvent(0, ev_chain, 0);
    k_edges<<<(P + 3) / 4, 256>>>(R, E, L1, (float*)d_out, P, n);
    k_diag <<<(n + 3) / 4, 256>>>((float*)d_out, n);
}

// round 17
// speedup vs baseline: 1.5968x; 1.0765x over previous
#include <cuda_runtime.h>
#include <math.h>
#include <stdint.h>

#define MAX_N  1024
#define EPS    1e-4f
#define ZCHUNK 32768           // bytes per bulk store (proven-fast config)
#define ZPER   4               // chunks per CTA

// ---- scratch (__device__ globals; no allocation allowed) ----
__device__ float g_diag[MAX_N * 64];    // per-node sum of R^T R
__device__ float g_dis [MAX_N * 64];    // per-node D^{-1/2}

// ---- TMA bulk-store zero (2048 CTAs x 128 thr x 32KB, ~4.9 TB/s) ----
__global__ void k_zero_tma(char* __restrict__ out, size_t total) {
    __shared__ __align__(128) char buf[ZCHUNK];
    float4* b4 = (float4*)buf;
    for (int t = threadIdx.x; t < ZCHUNK / 16; t += blockDim.x)
        b4[t] = make_float4(0.f, 0.f, 0.f, 0.f);
    __syncthreads();
    asm volatile("fence.proxy.async.shared::cta;" ::: "memory");
    if (threadIdx.x == 0) {
        uint32_t saddr;
        asm("{ .reg .u64 t; cvta.to.shared.u64 t, %1; cvt.u32.u64 %0, t; }"
            : "=r"(saddr) : "l"(buf));
        size_t base = (size_t)blockIdx.x * (ZPER * (size_t)ZCHUNK);
#pragma unroll
        for (int k = 0; k < ZPER; k++) {
            size_t off = base + (size_t)k * ZCHUNK;
            if (off >= total) break;
            size_t rem = total - off;
            unsigned len = (unsigned)(rem >= ZCHUNK ? ZCHUNK : rem);
            asm volatile(
                "cp.async.bulk.global.shared::cta.bulk_group [%0], [%1], %2;"
                :: "l"(out + off), "r"(saddr), "r"(len) : "memory");
        }
        asm volatile("cp.async.bulk.commit_group;" ::: "memory");
        asm volatile("cp.async.bulk.wait_group 0;" ::: "memory");
    }
}

// ---- k_ftf: smem-staged R^T R, atomically accumulated into g_diag[i] ----
__global__ void k_ftf(const float* __restrict__ R, const int* __restrict__ E, int P) {
    __shared__ float Rs[4][64];
    int sub = threadIdx.x >> 6;
    int t   = threadIdx.x & 63;
    int p   = blockIdx.x * 4 + sub;
    bool valid = (p < P);
    if (valid && t < 16)
        ((float4*)Rs[sub])[t] = ((const float4*)(R + (size_t)p * 64))[t];
    __syncthreads();
    if (!valid) return;
    int r = t >> 3, c = t & 7;
    float v = 0.f;
#pragma unroll
    for (int k = 0; k < 8; k++) v += Rs[sub][k * 8 + r] * Rs[sub][k * 8 + c];
    int i = E[2 * p];
    atomicAdd(&g_diag[i * 64 + t], v);
}

// ---- per-node D^{-1/2} via coupled Newton-Schulz; 4 nodes per 256-thread CTA ----
__global__ void k_ns(int n) {
    __shared__ float Y[4][64], Z[4][64], G[4][64], red[4][64];
    int sub = threadIdx.x >> 6;
    int t   = threadIdx.x & 63;
    int v   = blockIdx.x * 4 + sub;
    int vc  = (v < n) ? v : (n - 1);
    int r = t >> 3, c = t & 7;

    float a = g_diag[vc * 64 + r * 8 + c];
    float b = g_diag[vc * 64 + c * 8 + r];
    float d = 0.5f * (a + b) + ((r == c) ? EPS : 0.f);

    red[sub][t] = d * d;
    __syncthreads();
    if (t < 32) red[sub][t] += red[sub][t + 32];
    __syncthreads();
    if (t < 16) red[sub][t] += red[sub][t + 16];
    __syncthreads();
    if (t < 8)  red[sub][t] += red[sub][t + 8];
    __syncthreads();
    if (t < 4)  red[sub][t] += red[sub][t + 4];
    __syncthreads();
    if (t < 2)  red[sub][t] += red[sub][t + 2];
    __syncthreads();
    if (t == 0) red[sub][0] += red[sub][1];
    __syncthreads();
    float s = sqrtf(red[sub][0]);
    float inv_s = 1.f / s;

    Y[sub][t] = d * inv_s;
    Z[sub][t] = (r == c) ? 1.f : 0.f;
    __syncthreads();

    for (int it = 0; it < 24; it++) {
        float acc = 0.f;
#pragma unroll
        for (int k = 0; k < 8; k++) acc += Z[sub][r * 8 + k] * Y[sub][k * 8 + c];
        float g = ((r == c) ? 1.5f : 0.f) - 0.5f * acc;
        __syncthreads();
        G[sub][t] = g;
        __syncthreads();
        float ny = 0.f, nz = 0.f;
#pragma unroll
        for (int k = 0; k < 8; k++) {
            ny += Y[sub][r * 8 + k] * G[sub][k * 8 + c];
            nz += G[sub][r * 8 + k] * Z[sub][k * 8 + c];
        }
        __syncthreads();
        Y[sub][t] = ny;
        Z[sub][t] = nz;
        __syncthreads();
    }

    if (v < n) g_dis[v * 64 + t] = Z[sub][t] * rsqrtf(s);
}

// ---- k_edges PAIRED: one sub-block per UNDIRECTED edge p in [0, P/2).
//      C = (R_rev @ Dis_lo)^T @ (R_p @ Dis_hi)
//      out(lo,hi) = -sgn(L1[lo,hi]) * C ; out(hi,lo) = -sgn(L1[hi,lo]) * C^T ----
__global__ void k_edges(const float* __restrict__ R, const int* __restrict__ E,
                        const float* __restrict__ L1, float* __restrict__ out,
                        int P, int n) {
    __shared__ float Rp[4][64], Rr[4][64], DiS[4][64], DjS[4][64],
                     MT[4][64], NN[4][64], Cs[4][64];
    int half = P >> 1;
    int sub = threadIdx.x >> 6;
    int t   = threadIdx.x & 63;
    int p   = blockIdx.x * 4 + sub;       // undirected edge id (fwd directed id)
    bool valid = (p < half);
    int lo = 0, hi = 0;

    if (valid) {
        int2 e = ((const int2*)E)[p];     // (lo, hi)
        lo = e.x; hi = e.y;
        int rev = p + half;               // (hi, lo)
        int grp = t >> 4;
        int l   = t & 15;
        if (grp == 0)      ((float4*)Rp[sub])[l]  = ((const float4*)(R + (size_t)p * 64))[l];
        else if (grp == 1) ((float4*)Rr[sub])[l]  = ((const float4*)(R + (size_t)rev * 64))[l];
        else if (grp == 2) ((float4*)DiS[sub])[l] = ((const float4*)(g_dis + (size_t)lo * 64))[l];
        else               ((float4*)DjS[sub])[l] = ((const float4*)(g_dis + (size_t)hi * 64))[l];
    }
    __syncthreads();

    int r = t >> 3, c = t & 7;
    if (valid) {
        // M[r][c] = (R_rev @ Dis_lo)[r][c]   (store transposed into MT)
        float4 a0 = ((const float4*)(Rr[sub] + r * 8))[0];
        float4 a1 = ((const float4*)(Rr[sub] + r * 8))[1];
        const float* Dc = DiS[sub] + c;
        float m = a0.x * Dc[0]  + a0.y * Dc[8]  + a0.z * Dc[16] + a0.w * Dc[24]
                + a1.x * Dc[32] + a1.y * Dc[40] + a1.z * Dc[48] + a1.w * Dc[56];
        // N[r][c] = (R_p @ Dis_hi)[r][c]
        float4 b0 = ((const float4*)(Rp[sub] + r * 8))[0];
        float4 b1 = ((const float4*)(Rp[sub] + r * 8))[1];
        const float* Ec = DjS[sub] + c;
        float nn = b0.x * Ec[0]  + b0.y * Ec[8]  + b0.z * Ec[16] + b0.w * Ec[24]
                 + b1.x * Ec[32] + b1.y * Ec[40] + b1.z * Ec[48] + b1.w * Ec[56];
        MT[sub][c * 8 + r] = m;
        NN[sub][t] = nn;
    }
    __syncthreads();

    if (valid) {
        // C[r][c] = sum_k M[k][r] * N[k][c] = sum_k MT[r*8+k] * NN[k*8+c]
        float4 a0 = ((const float4*)(MT[sub] + r * 8))[0];
        float4 a1 = ((const float4*)(MT[sub] + r * 8))[1];
        const float* Bc = NN[sub] + c;
        float s = a0.x * Bc[0]  + a0.y * Bc[8]  + a0.z * Bc[16] + a0.w * Bc[24]
                + a1.x * Bc[32] + a1.y * Bc[40] + a1.z * Bc[48] + a1.w * Bc[56];
        Cs[sub][t] = s;
    }
    __syncthreads();

    if (valid) {
        float l1 = L1[(size_t)lo * n + hi];
        float l2 = L1[(size_t)hi * n + lo];
        float s1 = (l1 > 0.f) ? 1.f : ((l1 < 0.f) ? -1.f : 0.f);
        float s2 = (l2 > 0.f) ? 1.f : ((l2 < 0.f) ? -1.f : 0.f);
        size_t nd = (size_t)n * 8;
        // block (lo, hi): -s1 * C[r][c]
        out[((size_t)lo * 8 + r) * nd + (size_t)hi * 8 + c] = -s1 * Cs[sub][t];
        // block (hi, lo): -s2 * C^T  -> element [r][c] = -s2 * C[c][r]
        out[((size_t)hi * 8 + r) * nd + (size_t)lo * 8 + c] = -s2 * Cs[sub][c * 8 + r];
    }
}

// ---- k_diag: diagonal blocks Dis_v @ diag_v @ Dis_v, written directly ----
__global__ void k_diag(float* __restrict__ out, int n) {
    __shared__ float Di[4][64], B[4][64], T[4][64];
    int sub = threadIdx.x >> 6;
    int t   = threadIdx.x & 63;
    int v   = blockIdx.x * 4 + sub;
    bool valid = (v < n);
    if (valid) {
        if (t < 16)
            ((float4*)Di[sub])[t] = ((const float4*)(g_dis + (size_t)v * 64))[t];
        else if (t < 32)
            ((float4*)B[sub])[t - 16] = ((const float4*)(g_diag + (size_t)v * 64))[t - 16];
    }
    __syncthreads();
    int r = t >> 3, c = t & 7;
    if (valid) {
        float4 a0 = ((const float4*)(Di[sub] + r * 8))[0];
        float4 a1 = ((const float4*)(Di[sub] + r * 8))[1];
        const float* Bc = B[sub] + c;
        float s = a0.x * Bc[0]  + a0.y * Bc[8]  + a0.z * Bc[16] + a0.w * Bc[24]
                + a1.x * Bc[32] + a1.y * Bc[40] + a1.z * Bc[48] + a1.w * Bc[56];
        T[sub][t] = s;
    }
    __syncthreads();
    if (valid) {
        float4 a0 = ((const float4*)(T[sub] + r * 8))[0];
        float4 a1 = ((const float4*)(T[sub] + r * 8))[1];
        const float* Bc = Di[sub] + c;
        float s = a0.x * Bc[0]  + a0.y * Bc[8]  + a0.z * Bc[16] + a0.w * Bc[24]
                + a1.x * Bc[32] + a1.y * Bc[40] + a1.z * Bc[48] + a1.w * Bc[56];
        size_t nd = (size_t)n * 8;
        out[((size_t)v * 8 + r) * nd + (size_t)v * 8 + c] = s;
    }
}

extern "C" void kernel_launch(void* const* d_in, const int* in_sizes, int n_in,
                              void* d_out, int out_size) {
    const float* R  = (const float*)d_in[0];  // (P, 8, 8)
    const int*   E  = (const int*)  d_in[1];  // (P, 2)
    const float* L1 = (const float*)d_in[3];  // (n, n)

    int P = in_sizes[1] / 2;
    int n = (int)(sqrt((double)in_sizes[3]) + 0.5);

    // one-time host-side resources (streams/events are NOT device memory)
    static bool inited = false;
    static cudaStream_t side;
    static cudaEvent_t ev_fork, ev_chain;
    static void* diag_ptr;
    if (!inited) {
        cudaStreamCreateWithFlags(&side, cudaStreamNonBlocking);
        cudaEventCreateWithFlags(&ev_fork, cudaEventDisableTiming);
        cudaEventCreateWithFlags(&ev_chain, cudaEventDisableTiming);
        cudaGetSymbolAddress(&diag_ptr, g_diag);
        inited = true;
    }

    cudaEventRecord(ev_fork, 0);

    // side stream: ftf + ns (free if overlap happens, cheap if serial)
    cudaStreamWaitEvent(side, ev_fork, 0);
    cudaMemsetAsync(diag_ptr, 0, (size_t)n * 64 * sizeof(float), side);
    k_ftf<<<(P + 3) / 4, 256, 0, side>>>(R, E, P);
    k_ns <<<(n + 3) / 4, 256, 0, side>>>(n);
    cudaEventRecord(ev_chain, side);

    // main stream: TMA zero
    size_t total = (size_t)out_size * sizeof(float);
    size_t per_cta = (size_t)ZPER * ZCHUNK;
    int zgrid = (int)((total + per_cta - 1) / per_cta);
    k_zero_tma<<<zgrid, 128>>>((char*)d_out, total);

    // tail: paired edge writer + diag writer, directly into d_out
    cudaStreamWaitEvent(0, ev_chain, 0);
    int half = P >> 1;
    k_edges<<<(half + 3) / 4, 256>>>(R, E, L1, (float*)d_out, P, n);
    k_diag <<<(n + 3) / 4, 256>>>((float*)d_out, n);
}